// round 4
// baseline (speedup 1.0000x reference)
#include <cuda_runtime.h>

// Shapes (fixed): B=2, S=2048, D=1024, H=16, d=64
//  - head h of batch b is the contiguous block (b*2048 + h*128)*1024 viewed as [2048,64] row-major
//  - d_out = [ proj : 4194304 f32 ][ attn : 134217728 f32 ]

#define PROJ_ELEMS 4194304LL
#define HEAD_STRIDE 131072LL       // elements per (b,h) head block in Q/K/V/O
#define ATTN_STRIDE 4194304LL      // 2048*2048 per (b,h)

// Scratch (device globals: no allocations allowed)
__device__ float g_Q[4194304];
__device__ float g_K[4194304];
__device__ float g_V[4194304];
__device__ float g_O[4194304];

// ---------------------------------------------------------------------------
// Generic NT GEMM:  C[m,n] = alpha * sum_k A[m,k]*W[n,k]  (+ bias[n])
// A row-major [M,K], W row-major [N,K], C row-major [M,N].
// Tile 128x128, BK=16, 256 threads, 8x8 per thread.
// blockIdx.z offsets A/W/C by zsA/zsW/zsC elements (batched heads for scores).
// ---------------------------------------------------------------------------
__global__ __launch_bounds__(256) void gemm_nt(
    const float* __restrict__ A, const float* __restrict__ W,
    const float* __restrict__ bias, float* __restrict__ C,
    int M, int N, int K, float alpha,
    long zsA, long zsW, long zsC)
{
    A += (long)blockIdx.z * zsA;
    W += (long)blockIdx.z * zsW;
    C += (long)blockIdx.z * zsC;

    __shared__ float As[16][132];   // [k][m], padded
    __shared__ float Ws[16][132];   // [k][n], padded

    const int tid = threadIdx.x;
    const int tx  = tid & 15;       // n sub-tile
    const int ty  = tid >> 4;       // m sub-tile
    const int rowC = blockIdx.y * 128;
    const int colC = blockIdx.x * 128;

    const float* Ap = A + (long)rowC * K;
    const float* Wp = W + (long)colC * K;

    float acc[8][8];
    #pragma unroll
    for (int i = 0; i < 8; i++)
        #pragma unroll
        for (int j = 0; j < 8; j++) acc[i][j] = 0.f;

    for (int k0 = 0; k0 < K; k0 += 16) {
        float4 aV[2], wV[2];
        #pragma unroll
        for (int i = 0; i < 2; i++) {
            int l = tid + i * 256;
            int lr = l >> 2, ls = l & 3;       // row 0..127, k-segment 0..3
            aV[i] = *(const float4*)(Ap + (long)lr * K + k0 + ls * 4);
            wV[i] = *(const float4*)(Wp + (long)lr * K + k0 + ls * 4);
        }
        __syncthreads();
        #pragma unroll
        for (int i = 0; i < 2; i++) {
            int l = tid + i * 256;
            int lr = l >> 2, ls = l & 3;
            As[ls*4+0][lr] = aV[i].x; As[ls*4+1][lr] = aV[i].y;
            As[ls*4+2][lr] = aV[i].z; As[ls*4+3][lr] = aV[i].w;
            Ws[ls*4+0][lr] = wV[i].x; Ws[ls*4+1][lr] = wV[i].y;
            Ws[ls*4+2][lr] = wV[i].z; Ws[ls*4+3][lr] = wV[i].w;
        }
        __syncthreads();
        #pragma unroll
        for (int kk = 0; kk < 16; kk++) {
            float a[8], w[8];
            *(float4*)&a[0] = *(const float4*)&As[kk][ty*8];
            *(float4*)&a[4] = *(const float4*)&As[kk][ty*8 + 4];
            *(float4*)&w[0] = *(const float4*)&Ws[kk][tx*8];
            *(float4*)&w[4] = *(const float4*)&Ws[kk][tx*8 + 4];
            #pragma unroll
            for (int i = 0; i < 8; i++)
                #pragma unroll
                for (int j = 0; j < 8; j++)
                    acc[i][j] = fmaf(a[i], w[j], acc[i][j]);
        }
    }

    float bb[8];
    #pragma unroll
    for (int j = 0; j < 8; j++)
        bb[j] = bias ? bias[colC + tx*8 + j] : 0.f;

    #pragma unroll
    for (int i = 0; i < 8; i++) {
        long r = rowC + ty*8 + i;
        float o[8];
        #pragma unroll
        for (int j = 0; j < 8; j++) o[j] = fmaf(acc[i][j], alpha, bb[j]);
        *(float4*)(C + r * N + colC + tx*8)     = *(float4*)&o[0];
        *(float4*)(C + r * N + colC + tx*8 + 4) = *(float4*)&o[4];
    }
}

// ---------------------------------------------------------------------------
// Row softmax, in place. One block per row of 2048, 256 threads x 8 elems.
// ---------------------------------------------------------------------------
__global__ __launch_bounds__(256) void softmax_rows(float* __restrict__ attn)
{
    float* p = attn + (long)blockIdx.x * 2048;
    const int tid = threadIdx.x;
    const int warp = tid >> 5, lane = tid & 31;

    float v[8];
    #pragma unroll
    for (int i = 0; i < 8; i++) v[i] = p[tid + i*256];

    float m = v[0];
    #pragma unroll
    for (int i = 1; i < 8; i++) m = fmaxf(m, v[i]);
    #pragma unroll
    for (int off = 16; off; off >>= 1)
        m = fmaxf(m, __shfl_xor_sync(0xffffffffu, m, off));

    __shared__ float red[8];
    if (lane == 0) red[warp] = m;
    __syncthreads();
    float mm = red[0];
    #pragma unroll
    for (int w = 1; w < 8; w++) mm = fmaxf(mm, red[w]);

    float s = 0.f;
    #pragma unroll
    for (int i = 0; i < 8; i++) { v[i] = expf(v[i] - mm); s += v[i]; }
    #pragma unroll
    for (int off = 16; off; off >>= 1)
        s += __shfl_xor_sync(0xffffffffu, s, off);

    __syncthreads();                 // everyone done reading red (max)
    if (lane == 0) red[warp] = s;
    __syncthreads();
    float tot = 0.f;
    #pragma unroll
    for (int w = 0; w < 8; w++) tot += red[w];
    float inv = 1.f / tot;

    #pragma unroll
    for (int i = 0; i < 8; i++) p[tid + i*256] = v[i] * inv;
}

// ---------------------------------------------------------------------------
// O = attn @ Vh per (b,h).  NN GEMM: A [2048,2048] row-major, B [2048,64]
// row-major, C [2048,64]. Tile 128x64, BK=16, 256 threads, 8x4 per thread.
// ---------------------------------------------------------------------------
__global__ __launch_bounds__(256) void attn_v_gemm(
    const float* __restrict__ attn, const float* __restrict__ V,
    float* __restrict__ O)
{
    const long z = blockIdx.z;
    const float* Ap = attn + z * ATTN_STRIDE + (long)blockIdx.y * 128 * 2048;
    const float* Bp = V    + z * HEAD_STRIDE;
    float*       Cp = O    + z * HEAD_STRIDE + (long)blockIdx.y * 128 * 64;

    __shared__ float As[16][132];   // [k][m], padded
    __shared__ float Bs[16][64];    // [k][n]

    const int tid = threadIdx.x;
    const int tx  = tid & 15;       // n: tx*4
    const int ty  = tid >> 4;       // m: ty*8

    float acc[8][4];
    #pragma unroll
    for (int i = 0; i < 8; i++)
        #pragma unroll
        for (int j = 0; j < 4; j++) acc[i][j] = 0.f;

    for (int k0 = 0; k0 < 2048; k0 += 16) {
        float4 aV[2];
        #pragma unroll
        for (int i = 0; i < 2; i++) {
            int l = tid + i * 256;
            int lr = l >> 2, ls = l & 3;
            aV[i] = *(const float4*)(Ap + (long)lr * 2048 + k0 + ls * 4);
        }
        const int bk   = tid >> 4;      // 0..15
        const int bseg = tid & 15;      // 0..15
        float4 bV = *(const float4*)(Bp + (long)(k0 + bk) * 64 + bseg * 4);

        __syncthreads();
        #pragma unroll
        for (int i = 0; i < 2; i++) {
            int l = tid + i * 256;
            int lr = l >> 2, ls = l & 3;
            As[ls*4+0][lr] = aV[i].x; As[ls*4+1][lr] = aV[i].y;
            As[ls*4+2][lr] = aV[i].z; As[ls*4+3][lr] = aV[i].w;
        }
        *(float4*)&Bs[bk][bseg * 4] = bV;
        __syncthreads();

        #pragma unroll
        for (int kk = 0; kk < 16; kk++) {
            float a[8], b[4];
            *(float4*)&a[0] = *(const float4*)&As[kk][ty*8];
            *(float4*)&a[4] = *(const float4*)&As[kk][ty*8 + 4];
            *(float4*)&b[0] = *(const float4*)&Bs[kk][tx*4];
            #pragma unroll
            for (int i = 0; i < 8; i++)
                #pragma unroll
                for (int j = 0; j < 4; j++)
                    acc[i][j] = fmaf(a[i], b[j], acc[i][j]);
        }
    }

    #pragma unroll
    for (int i = 0; i < 8; i++) {
        *(float4*)(Cp + (long)(ty*8 + i) * 64 + tx*4) = *(float4*)&acc[i][0];
    }
}

// ---------------------------------------------------------------------------
extern "C" void kernel_launch(void* const* d_in, const int* in_sizes, int n_in,
                              void* d_out, int out_size)
{
    const float* pre_q = (const float*)d_in[0];
    const float* pre_k = (const float*)d_in[1];
    const float* pre_v = (const float*)d_in[2];
    const float* Wq = (const float*)d_in[3];
    const float* bq = (const float*)d_in[4];
    const float* Wk = (const float*)d_in[5];
    const float* bk = (const float*)d_in[6];
    const float* Wv = (const float*)d_in[7];
    const float* bv = (const float*)d_in[8];
    const float* Wo = (const float*)d_in[9];
    const float* bo = (const float*)d_in[10];

    float* proj = (float*)d_out;
    float* attn = proj + PROJ_ELEMS;

    float *q, *k, *v, *o;
    cudaGetSymbolAddress((void**)&q, g_Q);
    cudaGetSymbolAddress((void**)&k, g_K);
    cudaGetSymbolAddress((void**)&v, g_V);
    cudaGetSymbolAddress((void**)&o, g_O);

    const dim3 thr(256);

    // Q/K/V projections: [4096,1024] = pre_x @ W^T + b
    gemm_nt<<<dim3(8, 32, 1), thr>>>(pre_q, Wq, bq, q, 4096, 1024, 1024, 1.f, 0, 0, 0);
    gemm_nt<<<dim3(8, 32, 1), thr>>>(pre_k, Wk, bk, k, 4096, 1024, 1024, 1.f, 0, 0, 0);
    gemm_nt<<<dim3(8, 32, 1), thr>>>(pre_v, Wv, bv, v, 4096, 1024, 1024, 1.f, 0, 0, 0);

    // Scores per (b,h): [2048,64] @ [2048,64]^T * 1/8 -> attn region of d_out
    gemm_nt<<<dim3(16, 16, 32), thr>>>(q, k, nullptr, attn, 2048, 2048, 64, 0.125f,
                                       HEAD_STRIDE, HEAD_STRIDE, ATTN_STRIDE);

    // Softmax in place over all 65536 rows
    softmax_rows<<<65536, 256>>>(attn);

    // O = attn @ Vh per head
    attn_v_gemm<<<dim3(1, 16, 32), thr>>>(attn, v, o);

    // Output projection: proj = O @ Wo^T + bo
    gemm_nt<<<dim3(8, 32, 1), thr>>>(o, Wo, bo, proj, 4096, 1024, 1024, 1.f, 0, 0, 0);
}

// round 5
// speedup vs baseline: 1.0803x; 1.0803x over previous
#include <cuda_runtime.h>
#include <cstdint>

// Shapes (fixed): B=2, S=2048, D=1024, H=16, d=64
// head h of batch b = contiguous block (b*2048 + h*128)*1024 viewed as [2048,64] row-major
// d_out = [ proj : 4194304 f32 ][ attn : 134217728 f32 ]

#define PROJ_ELEMS 4194304LL
#define HEAD_STRIDE 131072LL       // elements per (b,h) head block in Q/K/V/O
#define ATTN_STRIDE 4194304LL      // 2048*2048 per (b,h)

__device__ float g_Q[4194304];
__device__ float g_K[4194304];
__device__ float g_V[4194304];
__device__ float g_O[4194304];

__device__ __forceinline__ float to_tf32(float x) {
    uint32_t u;
    asm("cvt.rna.tf32.f32 %0, %1;" : "=r"(u) : "f"(x));
    return __uint_as_float(u);
}

__device__ __forceinline__ void mma8(float* c,
    uint32_t a0, uint32_t a1, uint32_t a2, uint32_t a3,
    uint32_t b0, uint32_t b1)
{
    asm volatile(
        "mma.sync.aligned.m16n8k8.row.col.f32.tf32.tf32.f32 "
        "{%0,%1,%2,%3},{%4,%5,%6,%7},{%8,%9},{%0,%1,%2,%3};"
        : "+f"(c[0]), "+f"(c[1]), "+f"(c[2]), "+f"(c[3])
        : "r"(a0), "r"(a1), "r"(a2), "r"(a3), "r"(b0), "r"(b1));
}

// ---------------------------------------------------------------------------
// Tensor-core GEMM.  C[m,n] = alpha * sum_k A[m,k]*B'[k,n]  (+ bias[n])
//   A row-major [M,K].
//   B_KMAJOR=true : B is W[n][k] row-major (NT gemm, K contiguous)
//   B_KMAJOR=false: B is V[k][n] row-major (NN gemm, N contiguous)  [BN=64 only]
//   SPLIT=true: split-tf32 (3 mma passes) for ~fp32 accuracy.
// Block 128 x BN, BK=16, 256 threads (8 warps as 2x4), warp tile 64 x BN/4.
// blockIdx.z batches by zsA/zsB/zsC element strides.
// ---------------------------------------------------------------------------
template<int BN, int NI, bool SPLIT, bool B_KMAJOR>
__global__ __launch_bounds__(256) void gemm_tc(
    const float* __restrict__ A, const float* __restrict__ B,
    const float* __restrict__ bias, float* __restrict__ C,
    int M, int N, int K, float alpha,
    long zsA, long zsB, long zsC)
{
    A += (long)blockIdx.z * zsA;
    B += (long)blockIdx.z * zsB;
    C += (long)blockIdx.z * zsC;

    constexpr int NS = SPLIT ? 2 : 1;
    __shared__ float As[NS][16][132];
    __shared__ float Bs[NS][16][BN + 4];

    const int tid  = threadIdx.x;
    const int warp = tid >> 5, lane = tid & 31;
    const int g = lane >> 2, t = lane & 3;
    const int wm = warp >> 2, wn = warp & 3;
    constexpr int WN = BN / 4;

    const int rowC = blockIdx.y * 128;
    const int colC = blockIdx.x * BN;

    const float* Ap = A + (long)rowC * K;

    float acc[4][NI][4];
    #pragma unroll
    for (int mi = 0; mi < 4; mi++)
        #pragma unroll
        for (int ni = 0; ni < NI; ni++)
            #pragma unroll
            for (int r = 0; r < 4; r++) acc[mi][ni][r] = 0.f;

    constexpr int BIT = B_KMAJOR ? (BN / 64) : 1;

    for (int k0 = 0; k0 < K; k0 += 16) {
        // -------- global loads --------
        float4 aV[2];
        #pragma unroll
        for (int i = 0; i < 2; i++) {
            int l = tid + i * 256, lr = l >> 2, ls = l & 3;
            aV[i] = *(const float4*)(Ap + (long)lr * K + k0 + ls * 4);
        }
        float4 bV[BIT];
        if constexpr (B_KMAJOR) {
            const float* Wp = B + (long)colC * K;
            #pragma unroll
            for (int i = 0; i < BIT; i++) {
                int l = tid + i * 256, lr = l >> 2, ls = l & 3;
                bV[i] = *(const float4*)(Wp + (long)lr * K + k0 + ls * 4);
            }
        } else {
            // B tile [16][BN] direct: lr = k row, lc = n segment
            int lr = tid >> 4, lc = tid & 15;
            bV[0] = *(const float4*)(B + (long)(k0 + lr) * N + colC + lc * 4);
        }

        __syncthreads();
        // -------- smem stores (tf32 round + optional split) --------
        #pragma unroll
        for (int i = 0; i < 2; i++) {
            int l = tid + i * 256, lr = l >> 2, ls = l & 3;
            float vals[4] = {aV[i].x, aV[i].y, aV[i].z, aV[i].w};
            #pragma unroll
            for (int c = 0; c < 4; c++) {
                float h = to_tf32(vals[c]);
                As[0][ls * 4 + c][lr] = h;
                if constexpr (SPLIT) As[1][ls * 4 + c][lr] = vals[c] - h;
            }
        }
        if constexpr (B_KMAJOR) {
            #pragma unroll
            for (int i = 0; i < BIT; i++) {
                int l = tid + i * 256, lr = l >> 2, ls = l & 3;
                float vals[4] = {bV[i].x, bV[i].y, bV[i].z, bV[i].w};
                #pragma unroll
                for (int c = 0; c < 4; c++) {
                    float h = to_tf32(vals[c]);
                    Bs[0][ls * 4 + c][lr] = h;
                    if constexpr (SPLIT) Bs[1][ls * 4 + c][lr] = vals[c] - h;
                }
            }
        } else {
            int lr = tid >> 4, lc = tid & 15;
            float vals[4] = {bV[0].x, bV[0].y, bV[0].z, bV[0].w};
            #pragma unroll
            for (int c = 0; c < 4; c++) {
                float h = to_tf32(vals[c]);
                Bs[0][lr][lc * 4 + c] = h;
                if constexpr (SPLIT) Bs[1][lr][lc * 4 + c] = vals[c] - h;
            }
        }
        __syncthreads();

        // -------- warp mma over the 16-deep tile (two k=8 steps) --------
        #pragma unroll
        for (int ks = 0; ks < 2; ks++) {
            const int kb = ks * 8;
            uint32_t bh[NI][2], bl[NI][2];
            #pragma unroll
            for (int ni = 0; ni < NI; ni++) {
                int cn = wn * WN + ni * 8 + g;
                bh[ni][0] = __float_as_uint(Bs[0][kb + t][cn]);
                bh[ni][1] = __float_as_uint(Bs[0][kb + t + 4][cn]);
                if constexpr (SPLIT) {
                    bl[ni][0] = __float_as_uint(Bs[1][kb + t][cn]);
                    bl[ni][1] = __float_as_uint(Bs[1][kb + t + 4][cn]);
                }
            }
            #pragma unroll
            for (int mi = 0; mi < 4; mi++) {
                int mc = wm * 64 + mi * 16;
                uint32_t ah0 = __float_as_uint(As[0][kb + t][mc + g]);
                uint32_t ah1 = __float_as_uint(As[0][kb + t][mc + g + 8]);
                uint32_t ah2 = __float_as_uint(As[0][kb + t + 4][mc + g]);
                uint32_t ah3 = __float_as_uint(As[0][kb + t + 4][mc + g + 8]);
                uint32_t al0 = 0, al1 = 0, al2 = 0, al3 = 0;
                if constexpr (SPLIT) {
                    al0 = __float_as_uint(As[1][kb + t][mc + g]);
                    al1 = __float_as_uint(As[1][kb + t][mc + g + 8]);
                    al2 = __float_as_uint(As[1][kb + t + 4][mc + g]);
                    al3 = __float_as_uint(As[1][kb + t + 4][mc + g + 8]);
                }
                #pragma unroll
                for (int ni = 0; ni < NI; ni++) {
                    mma8(acc[mi][ni], ah0, ah1, ah2, ah3, bh[ni][0], bh[ni][1]);
                    if constexpr (SPLIT) {
                        mma8(acc[mi][ni], ah0, ah1, ah2, ah3, bl[ni][0], bl[ni][1]);
                        mma8(acc[mi][ni], al0, al1, al2, al3, bh[ni][0], bh[ni][1]);
                    }
                }
            }
        }
        __syncthreads();
    }

    // -------- epilogue --------
    #pragma unroll
    for (int mi = 0; mi < 4; mi++) {
        #pragma unroll
        for (int ni = 0; ni < NI; ni++) {
            int r0 = rowC + wm * 64 + mi * 16 + g;
            int cc = colC + wn * WN + ni * 8 + 2 * t;
            float b0 = bias ? bias[cc]     : 0.f;
            float b1 = bias ? bias[cc + 1] : 0.f;
            float2 o0 = { fmaf(acc[mi][ni][0], alpha, b0),
                          fmaf(acc[mi][ni][1], alpha, b1) };
            float2 o1 = { fmaf(acc[mi][ni][2], alpha, b0),
                          fmaf(acc[mi][ni][3], alpha, b1) };
            *(float2*)(C + (long)r0 * N + cc)       = o0;
            *(float2*)(C + (long)(r0 + 8) * N + cc) = o1;
        }
    }
}

// ---------------------------------------------------------------------------
// Row softmax, in place. One block per row of 2048, 256 threads x 8 elems.
// ---------------------------------------------------------------------------
__global__ __launch_bounds__(256) void softmax_rows(float* __restrict__ attn)
{
    float* p = attn + (long)blockIdx.x * 2048;
    const int tid = threadIdx.x;
    const int warp = tid >> 5, lane = tid & 31;

    float v[8];
    #pragma unroll
    for (int i = 0; i < 8; i++) v[i] = p[tid + i * 256];

    float m = v[0];
    #pragma unroll
    for (int i = 1; i < 8; i++) m = fmaxf(m, v[i]);
    #pragma unroll
    for (int off = 16; off; off >>= 1)
        m = fmaxf(m, __shfl_xor_sync(0xffffffffu, m, off));

    __shared__ float red[8];
    if (lane == 0) red[warp] = m;
    __syncthreads();
    float mm = red[0];
    #pragma unroll
    for (int w = 1; w < 8; w++) mm = fmaxf(mm, red[w]);

    float s = 0.f;
    #pragma unroll
    for (int i = 0; i < 8; i++) { v[i] = expf(v[i] - mm); s += v[i]; }
    #pragma unroll
    for (int off = 16; off; off >>= 1)
        s += __shfl_xor_sync(0xffffffffu, s, off);

    __syncthreads();
    if (lane == 0) red[warp] = s;
    __syncthreads();
    float tot = 0.f;
    #pragma unroll
    for (int w = 0; w < 8; w++) tot += red[w];
    float inv = 1.f / tot;

    #pragma unroll
    for (int i = 0; i < 8; i++) p[tid + i * 256] = v[i] * inv;
}

// ---------------------------------------------------------------------------
extern "C" void kernel_launch(void* const* d_in, const int* in_sizes, int n_in,
                              void* d_out, int out_size)
{
    const float* pre_q = (const float*)d_in[0];
    const float* pre_k = (const float*)d_in[1];
    const float* pre_v = (const float*)d_in[2];
    const float* Wq = (const float*)d_in[3];
    const float* bq = (const float*)d_in[4];
    const float* Wk = (const float*)d_in[5];
    const float* bk = (const float*)d_in[6];
    const float* Wv = (const float*)d_in[7];
    const float* bv = (const float*)d_in[8];
    const float* Wo = (const float*)d_in[9];
    const float* bo = (const float*)d_in[10];

    float* proj = (float*)d_out;
    float* attn = proj + PROJ_ELEMS;

    float *q, *k, *v, *o;
    cudaGetSymbolAddress((void**)&q, g_Q);
    cudaGetSymbolAddress((void**)&k, g_K);
    cudaGetSymbolAddress((void**)&v, g_V);
    cudaGetSymbolAddress((void**)&o, g_O);

    const dim3 thr(256);

    // Q/K/V projections: [4096,1024] = pre_x @ W^T + b   (split-tf32, K=1024)
    gemm_tc<128, 4, true, true><<<dim3(8, 32, 1), thr>>>(pre_q, Wq, bq, q, 4096, 1024, 1024, 1.f, 0, 0, 0);
    gemm_tc<128, 4, true, true><<<dim3(8, 32, 1), thr>>>(pre_k, Wk, bk, k, 4096, 1024, 1024, 1.f, 0, 0, 0);
    gemm_tc<128, 4, true, true><<<dim3(8, 32, 1), thr>>>(pre_v, Wv, bv, v, 4096, 1024, 1024, 1.f, 0, 0, 0);

    // Scores per (b,h): [2048,64] @ [2048,64]^T * 1/8 -> attn region (plain tf32, K=64)
    gemm_tc<128, 4, false, true><<<dim3(16, 16, 32), thr>>>(q, k, nullptr, attn, 2048, 2048, 64, 0.125f,
                                                            HEAD_STRIDE, HEAD_STRIDE, ATTN_STRIDE);

    // Softmax in place over all 65536 rows
    softmax_rows<<<65536, 256>>>(attn);

    // O = attn @ Vh per head  (NN, BN=64, split-tf32, K=2048)
    gemm_tc<64, 2, true, false><<<dim3(1, 16, 32), thr>>>(attn, v, nullptr, o, 2048, 64, 2048, 1.f,
                                                          ATTN_STRIDE, HEAD_STRIDE, HEAD_STRIDE);

    // Output projection: proj = O @ Wo^T + bo   (split-tf32, K=1024)
    gemm_tc<128, 4, true, true><<<dim3(8, 32, 1), thr>>>(o, Wo, bo, proj, 4096, 1024, 1024, 1.f, 0, 0, 0);
}

// round 6
// speedup vs baseline: 1.4506x; 1.3429x over previous
#include <cuda_runtime.h>
#include <cuda_bf16.h>
#include <cstdint>

// Shapes (fixed): B=2, S=2048, D=1024, H=16, d=64
// head h of batch b = contiguous block (b*2048 + h*128)*1024 viewed as [2048,64] row-major
// d_out = [ proj : 4194304 f32 ][ attn : 134217728 f32 ]

#define PROJ_ELEMS 4194304LL
#define HEAD_STRIDE 131072LL
#define ATTN_STRIDE 4194304LL

__device__ float g_Q[4194304];
__device__ float g_K[4194304];
__device__ float g_V[4194304];
__device__ float g_O[4194304];

__device__ __forceinline__ void split_bf16(float x, __nv_bfloat16& h, __nv_bfloat16& l) {
    h = __float2bfloat16(x);
    l = __float2bfloat16(x - __bfloat162float(h));
}

__device__ __forceinline__ uint32_t smem_u32(const void* p) {
    return (uint32_t)__cvta_generic_to_shared(p);
}

__device__ __forceinline__ void ldmx4(uint32_t& r0, uint32_t& r1, uint32_t& r2, uint32_t& r3,
                                      uint32_t addr) {
    asm volatile("ldmatrix.sync.aligned.m8n8.x4.shared.b16 {%0,%1,%2,%3}, [%4];"
                 : "=r"(r0), "=r"(r1), "=r"(r2), "=r"(r3) : "r"(addr));
}

__device__ __forceinline__ void mma16(float* c, const uint32_t* a, const uint32_t* b) {
    asm volatile(
        "mma.sync.aligned.m16n8k16.row.col.f32.bf16.bf16.f32 "
        "{%0,%1,%2,%3},{%4,%5,%6,%7},{%8,%9},{%0,%1,%2,%3};"
        : "+f"(c[0]), "+f"(c[1]), "+f"(c[2]), "+f"(c[3])
        : "r"(a[0]), "r"(a[1]), "r"(a[2]), "r"(a[3]), "r"(b[0]), "r"(b[1]));
}

// ---------------------------------------------------------------------------
// Split-bf16 tensor-core GEMM: C[m,n] = alpha * sum_k A[m,k]*B'[k,n] (+bias[n])
//   A row-major [M,K].
//   B_KMAJOR=true : B = W[n][k] row-major (NT)
//   B_KMAJOR=false: B = V[k][n] row-major (NN), BN=64 only
// Block 128 x BN, BK=32, 256 threads (8 warps, 2x4), warp tile 64 x BN/4.
// Each fp32 operand split into bf16 hi+lo; 3 mma passes (hi*hi, hi*lo, lo*hi).
// ---------------------------------------------------------------------------
template<int BN, bool B_KMAJOR>
__global__ __launch_bounds__(256) void gemm_bf16s(
    const float* __restrict__ A, const float* __restrict__ B,
    const float* __restrict__ bias, float* __restrict__ C,
    int M, int N, int K, float alpha,
    long zsA, long zsB, long zsC)
{
    A += (long)blockIdx.z * zsA;
    B += (long)blockIdx.z * zsB;
    C += (long)blockIdx.z * zsC;

    constexpr int NI  = BN / 32;     // n-fragments (8 wide) per warp
    constexpr int PAD = 40;          // bf16 per smem row (32 data + 8 pad) -> conflict-free ldmatrix

    __shared__ __nv_bfloat16 Ah[128 * PAD], Al[128 * PAD];
    __shared__ __nv_bfloat16 Bh[BN * PAD],  Bl[BN * PAD];

    const int tid  = threadIdx.x;
    const int warp = tid >> 5, lane = tid & 31;
    const int g = lane >> 2, t = lane & 3;
    const int wm = warp >> 2, wn = warp & 3;

    const int rowC = blockIdx.y * 128;
    const int colC = blockIdx.x * BN;
    const float* Ap = A + (long)rowC * K;

    float acc[4][NI][4];
    #pragma unroll
    for (int mi = 0; mi < 4; mi++)
        #pragma unroll
        for (int ni = 0; ni < NI; ni++)
            #pragma unroll
            for (int r = 0; r < 4; r++) acc[mi][ni][r] = 0.f;

    // ldmatrix per-lane source row/k-offset (same pattern for A and B tiles)
    const int lrow = lane & 15;                 // row within 16-row fragment
    const int lkof = (lane & 16) >> 1;          // 0 or 8 (k half)

    for (int k0 = 0; k0 < K; k0 += 32) {
        // ---------------- global loads ----------------
        float4 aV[4];
        #pragma unroll
        for (int i = 0; i < 4; i++) {
            int l = tid + i * 256, lr = l >> 3, ls = l & 7;
            aV[i] = *(const float4*)(Ap + (long)lr * K + k0 + ls * 4);
        }
        constexpr int BIT = B_KMAJOR ? (BN / 32) : 2;
        float4 bV[BIT];
        if constexpr (B_KMAJOR) {
            const float* Wp = B + (long)colC * K;
            #pragma unroll
            for (int i = 0; i < BIT; i++) {
                int l = tid + i * 256, lr = l >> 3, ls = l & 7;
                bV[i] = *(const float4*)(Wp + (long)lr * K + k0 + ls * 4);
            }
        } else {
            #pragma unroll
            for (int i = 0; i < 2; i++) {
                int l = tid + i * 256, lr = l >> 4, lc = l & 15;
                bV[i] = *(const float4*)(B + (long)(k0 + lr) * N + colC + lc * 4);
            }
        }

        __syncthreads();
        // ---------------- smem stores (split) ----------------
        #pragma unroll
        for (int i = 0; i < 4; i++) {
            int l = tid + i * 256, lr = l >> 3, ls = l & 7;
            float vals[4] = {aV[i].x, aV[i].y, aV[i].z, aV[i].w};
            #pragma unroll
            for (int c = 0; c < 4; c++) {
                __nv_bfloat16 h, lo;
                split_bf16(vals[c], h, lo);
                Ah[lr * PAD + ls * 4 + c] = h;
                Al[lr * PAD + ls * 4 + c] = lo;
            }
        }
        if constexpr (B_KMAJOR) {
            #pragma unroll
            for (int i = 0; i < BIT; i++) {
                int l = tid + i * 256, lr = l >> 3, ls = l & 7;
                float vals[4] = {bV[i].x, bV[i].y, bV[i].z, bV[i].w};
                #pragma unroll
                for (int c = 0; c < 4; c++) {
                    __nv_bfloat16 h, lo;
                    split_bf16(vals[c], h, lo);
                    Bh[lr * PAD + ls * 4 + c] = h;
                    Bl[lr * PAD + ls * 4 + c] = lo;
                }
            }
        } else {
            #pragma unroll
            for (int i = 0; i < 2; i++) {
                int l = tid + i * 256, lr = l >> 4, lc = l & 15;
                float vals[4] = {bV[i].x, bV[i].y, bV[i].z, bV[i].w};
                #pragma unroll
                for (int c = 0; c < 4; c++) {
                    __nv_bfloat16 h, lo;
                    split_bf16(vals[c], h, lo);
                    Bh[(lc * 4 + c) * PAD + lr] = h;
                    Bl[(lc * 4 + c) * PAD + lr] = lo;
                }
            }
        }
        __syncthreads();

        // ---------------- mma: two k16 steps ----------------
        #pragma unroll
        for (int ks = 0; ks < 2; ks++) {
            const int kb = ks * 16;
            uint32_t bh[NI][2], bl[NI][2];
            #pragma unroll
            for (int p = 0; p < NI / 2; p++) {
                int n = wn * (BN / 4) + p * 16;
                uint32_t addr_h = smem_u32(&Bh[(n + lrow) * PAD + kb + lkof]);
                uint32_t addr_l = smem_u32(&Bl[(n + lrow) * PAD + kb + lkof]);
                uint32_t r0, r1, r2, r3;
                ldmx4(r0, r1, r2, r3, addr_h);
                bh[2*p][0] = r0; bh[2*p+1][0] = r1; bh[2*p][1] = r2; bh[2*p+1][1] = r3;
                ldmx4(r0, r1, r2, r3, addr_l);
                bl[2*p][0] = r0; bl[2*p+1][0] = r1; bl[2*p][1] = r2; bl[2*p+1][1] = r3;
            }
            #pragma unroll
            for (int mi = 0; mi < 4; mi++) {
                int m = wm * 64 + mi * 16;
                uint32_t ah[4], al[4];
                ldmx4(ah[0], ah[1], ah[2], ah[3], smem_u32(&Ah[(m + lrow) * PAD + kb + lkof]));
                ldmx4(al[0], al[1], al[2], al[3], smem_u32(&Al[(m + lrow) * PAD + kb + lkof]));
                #pragma unroll
                for (int ni = 0; ni < NI; ni++) {
                    mma16(acc[mi][ni], ah, bh[ni]);   // hi*hi
                    mma16(acc[mi][ni], ah, bl[ni]);   // hi*lo
                    mma16(acc[mi][ni], al, bh[ni]);   // lo*hi
                }
            }
        }
        __syncthreads();
    }

    // ---------------- epilogue ----------------
    #pragma unroll
    for (int mi = 0; mi < 4; mi++) {
        #pragma unroll
        for (int ni = 0; ni < NI; ni++) {
            int r0 = rowC + wm * 64 + mi * 16 + g;
            int cc = colC + wn * (BN / 4) + ni * 8 + 2 * t;
            float b0 = bias ? bias[cc]     : 0.f;
            float b1 = bias ? bias[cc + 1] : 0.f;
            float2 o0 = { fmaf(acc[mi][ni][0], alpha, b0),
                          fmaf(acc[mi][ni][1], alpha, b1) };
            float2 o1 = { fmaf(acc[mi][ni][2], alpha, b0),
                          fmaf(acc[mi][ni][3], alpha, b1) };
            *(float2*)(C + (long)r0 * N + cc)       = o0;
            *(float2*)(C + (long)(r0 + 8) * N + cc) = o1;
        }
    }
}

// ---------------------------------------------------------------------------
// Row softmax, in place. One block per row of 2048, 256 threads x 8 elems.
// ---------------------------------------------------------------------------
__global__ __launch_bounds__(256) void softmax_rows(float* __restrict__ attn)
{
    float* p = attn + (long)blockIdx.x * 2048;
    const int tid = threadIdx.x;
    const int warp = tid >> 5, lane = tid & 31;

    float v[8];
    #pragma unroll
    for (int i = 0; i < 8; i++) v[i] = p[tid + i * 256];

    float m = v[0];
    #pragma unroll
    for (int i = 1; i < 8; i++) m = fmaxf(m, v[i]);
    #pragma unroll
    for (int off = 16; off; off >>= 1)
        m = fmaxf(m, __shfl_xor_sync(0xffffffffu, m, off));

    __shared__ float red[8];
    if (lane == 0) red[warp] = m;
    __syncthreads();
    float mm = red[0];
    #pragma unroll
    for (int w = 1; w < 8; w++) mm = fmaxf(mm, red[w]);

    float s = 0.f;
    #pragma unroll
    for (int i = 0; i < 8; i++) { v[i] = expf(v[i] - mm); s += v[i]; }
    #pragma unroll
    for (int off = 16; off; off >>= 1)
        s += __shfl_xor_sync(0xffffffffu, s, off);

    __syncthreads();
    if (lane == 0) red[warp] = s;
    __syncthreads();
    float tot = 0.f;
    #pragma unroll
    for (int w = 0; w < 8; w++) tot += red[w];
    float inv = 1.f / tot;

    #pragma unroll
    for (int i = 0; i < 8; i++) p[tid + i * 256] = v[i] * inv;
}

// ---------------------------------------------------------------------------
extern "C" void kernel_launch(void* const* d_in, const int* in_sizes, int n_in,
                              void* d_out, int out_size)
{
    const float* pre_q = (const float*)d_in[0];
    const float* pre_k = (const float*)d_in[1];
    const float* pre_v = (const float*)d_in[2];
    const float* Wq = (const float*)d_in[3];
    const float* bq = (const float*)d_in[4];
    const float* Wk = (const float*)d_in[5];
    const float* bk = (const float*)d_in[6];
    const float* Wv = (const float*)d_in[7];
    const float* bv = (const float*)d_in[8];
    const float* Wo = (const float*)d_in[9];
    const float* bo = (const float*)d_in[10];

    float* proj = (float*)d_out;
    float* attn = proj + PROJ_ELEMS;

    float *q, *k, *v, *o;
    cudaGetSymbolAddress((void**)&q, g_Q);
    cudaGetSymbolAddress((void**)&k, g_K);
    cudaGetSymbolAddress((void**)&v, g_V);
    cudaGetSymbolAddress((void**)&o, g_O);

    const dim3 thr(256);

    // Q/K/V projections: [4096,1024] = pre_x @ W^T + b
    gemm_bf16s<128, true><<<dim3(8, 32, 1), thr>>>(pre_q, Wq, bq, q, 4096, 1024, 1024, 1.f, 0, 0, 0);
    gemm_bf16s<128, true><<<dim3(8, 32, 1), thr>>>(pre_k, Wk, bk, k, 4096, 1024, 1024, 1.f, 0, 0, 0);
    gemm_bf16s<128, true><<<dim3(8, 32, 1), thr>>>(pre_v, Wv, bv, v, 4096, 1024, 1024, 1.f, 0, 0, 0);

    // Scores per (b,h): [2048,64] @ [2048,64]^T * 1/8 -> attn region of d_out
    gemm_bf16s<128, true><<<dim3(16, 16, 32), thr>>>(q, k, nullptr, attn, 2048, 2048, 64, 0.125f,
                                                     HEAD_STRIDE, HEAD_STRIDE, ATTN_STRIDE);

    // Softmax in place over all 65536 rows
    softmax_rows<<<65536, 256>>>(attn);

    // O = attn @ Vh per head (NN, BN=64)
    gemm_bf16s<64, false><<<dim3(1, 16, 32), thr>>>(attn, v, nullptr, o, 2048, 64, 2048, 1.f,
                                                    ATTN_STRIDE, HEAD_STRIDE, HEAD_STRIDE);

    // Output projection: proj = O @ Wo^T + bo
    gemm_bf16s<128, true><<<dim3(8, 32, 1), thr>>>(o, Wo, bo, proj, 4096, 1024, 1024, 1.f, 0, 0, 0);
}